// round 5
// baseline (speedup 1.0000x reference)
#include <cuda_runtime.h>
#include <cuda_fp16.h>
#include <math.h>

#define B_ROWS 4096
#define T_LEN  8192
#define SCAN_THREADS 512
#define NWARPS (SCAN_THREADS / 32)     // 16
#define CHUNK (T_LEN / SCAN_THREADS)   // 16
#define GAMMA 0.99f
#define GAMMA16 0.8514577710948755f    // 0.99^16
#define EPS_N 1e-9f

// Scratch (device globals; no allocations allowed).
__device__ float    g_row_sum[B_ROWS];
__device__ float    g_row_inv[B_ROWS];
__device__ float    g_mean_val;
__device__ unsigned g_count;           // zero-init; atomicInc wraps -> self-reset per launch
// fp16 staging for unnormalized returns: 64 MB, fits in L2 (126 MB).
__device__ __align__(128) __half g_ret_h[(size_t)B_ROWS * T_LEN];

// ───────────────────────── scan: one block per row ─────────────────────────
// x_t = r_t + a_t * x_{t+1},  a_t = GAMMA*(1-done_t),  done in {0,1} exactly.
__global__ __launch_bounds__(SCAN_THREADS, 3)
void scan_kernel(const float* __restrict__ rewards,
                 const float* __restrict__ dones)
{
    const int row  = blockIdx.x;
    const int tid  = threadIdx.x;
    const int lane = tid & 31;
    const int wid  = tid >> 5;
    const size_t row_off = (size_t)row * T_LEN;
    const int base = tid * CHUNK;

    float r[CHUNK];
    unsigned mask = 0;                 // bit t set -> done_t == 1 -> a_t == 0

    const float4* r4 = reinterpret_cast<const float4*>(rewards + row_off + base);
    const float4* d4 = reinterpret_cast<const float4*>(dones   + row_off + base);
#pragma unroll
    for (int i = 0; i < CHUNK / 4; i++) {
        float4 rv = __ldcs(r4 + i);
        float4 dv = __ldcs(d4 + i);
        r[i*4+0] = rv.x; r[i*4+1] = rv.y; r[i*4+2] = rv.z; r[i*4+3] = rv.w;
        mask |= (dv.x != 0.0f ? 1u : 0u) << (i*4+0);
        mask |= (dv.y != 0.0f ? 1u : 0u) << (i*4+1);
        mask |= (dv.z != 0.0f ? 1u : 0u) << (i*4+2);
        mask |= (dv.w != 0.0f ? 1u : 0u) << (i*4+3);
    }

    // Compose chunk into affine map (A, B): x_left = B + A * x_right.
    float A  = (mask == 0u) ? GAMMA16 : 0.0f;
    float Bc = 0.0f;
#pragma unroll
    for (int t = CHUNK - 1; t >= 0; t--) {
        float f = fmaf(GAMMA, Bc, r[t]);
        Bc = (mask & (1u << t)) ? r[t] : f;
    }

    // Warp-level inclusive SUFFIX scan via shuffles.
#pragma unroll
    for (int d = 1; d < 32; d <<= 1) {
        float A2 = __shfl_down_sync(0xFFFFFFFFu, A, d);
        float B2 = __shfl_down_sync(0xFFFFFFFFu, Bc, d);
        if (lane + d < 32) {
            Bc = fmaf(A, B2, Bc);
            A  = A * A2;
        }
    }

    __shared__ float sWA[NWARPS];
    __shared__ float sWB[NWARPS];
    __shared__ float sCB[NWARPS];
    if (lane == 0) { sWA[wid] = A; sWB[wid] = Bc; }
    __syncthreads();

    if (wid == 0) {
        float wA = (lane < NWARPS) ? sWA[lane] : 1.0f;
        float wB = (lane < NWARPS) ? sWB[lane] : 0.0f;
#pragma unroll
        for (int d = 1; d < NWARPS; d <<= 1) {
            float A2 = __shfl_down_sync(0xFFFFFFFFu, wA, d);
            float B2 = __shfl_down_sync(0xFFFFFFFFu, wB, d);
            if (lane + d < NWARPS) {
                wB = fmaf(wA, B2, wB);
                wA = wA * A2;
            }
        }
        float eB = __shfl_down_sync(0xFFFFFFFFu, wB, 1);
        if (lane == NWARPS - 1) eB = 0.0f;
        if (lane < NWARPS) sCB[lane] = eB;
    }
    __syncthreads();

    float cB   = sCB[wid];
    float totB = fmaf(A, cB, Bc);
    float carry = __shfl_down_sync(0xFFFFFFFFu, totB, 1);
    if (lane == 31) carry = cB;        // tid==511 -> cB==0, correct

    // Replay chunk with true carry; values + row moments (f32 precision).
    float sum = 0.0f, sq = 0.0f;
#pragma unroll
    for (int t = CHUNK - 1; t >= 0; t--) {
        float f = fmaf(GAMMA, carry, r[t]);
        carry = (mask & (1u << t)) ? r[t] : f;
        r[t] = carry;
        sum += carry;
        sq = fmaf(carry, carry, sq);
    }

    // fp16 staging store (default policy -> allocate in L2; consumed by norm).
    __half2 h[CHUNK / 2];
#pragma unroll
    for (int i = 0; i < CHUNK / 2; i++)
        h[i] = __floats2half2_rn(r[2*i], r[2*i+1]);
    uint4* dst = reinterpret_cast<uint4*>(g_ret_h + row_off + base);
    const uint4* src = reinterpret_cast<const uint4*>(h);
    dst[0] = src[0];
    dst[1] = src[1];

    // Block reduction of (sum, sq).
#pragma unroll
    for (int d = 16; d > 0; d >>= 1) {
        sum += __shfl_down_sync(0xFFFFFFFFu, sum, d);
        sq  += __shfl_down_sync(0xFFFFFFFFu, sq,  d);
    }
    __shared__ float sS[NWARPS];
    __shared__ float sQ[NWARPS];
    if (lane == 0) { sS[wid] = sum; sQ[wid] = sq; }
    __syncthreads();
    if (tid < 32) {
        float ts = (lane < NWARPS) ? sS[lane] : 0.0f;
        float tq = (lane < NWARPS) ? sQ[lane] : 0.0f;
#pragma unroll
        for (int d = NWARPS / 2; d > 0; d >>= 1) {
            ts += __shfl_down_sync(0xFFFFFFFFu, ts, d);
            tq += __shfl_down_sync(0xFFFFFFFFu, tq, d);
        }
        if (lane == 0) {
            float mean = ts / (float)T_LEN;
            float var  = (tq - ts * mean) / (float)(T_LEN - 1);   // ddof=1
            g_row_sum[row] = ts;
            g_row_inv[row] = 1.0f / (sqrtf(fmaxf(var, 0.0f)) + EPS_N);
        }
    }

    // Last block to finish reduces the 4096 row sums -> global mean.
    __shared__ unsigned s_last;
    if (tid == 0) {
        __threadfence();
        unsigned prev = atomicInc(&g_count, B_ROWS - 1);
        s_last = (prev == B_ROWS - 1) ? 1u : 0u;
    }
    __syncthreads();
    if (s_last) {
        float s = 0.0f;
#pragma unroll
        for (int i = 0; i < B_ROWS / SCAN_THREADS; i++)
            s += __ldcg(&g_row_sum[tid + i * SCAN_THREADS]);
#pragma unroll
        for (int d = 16; d > 0; d >>= 1)
            s += __shfl_down_sync(0xFFFFFFFFu, s, d);
        if (lane == 0) sS[wid] = s;
        __syncthreads();
        if (tid < 32) {
            float t = (lane < NWARPS) ? sS[lane] : 0.0f;
#pragma unroll
            for (int d = 16; d > 0; d >>= 1)
                t += __shfl_down_sync(0xFFFFFFFFu, t, d);
            if (tid == 0)
                g_mean_val = t / ((float)B_ROWS * (float)T_LEN);
        }
    }
}

// ── normalize: read fp16 staging (L2-resident), write f32 out (streaming) ──
// One block per row: 256 threads × 32 elements = 8192.
// 4 independent uint4 loads per thread (MLP=4), then 8 float4 streaming stores.
// After the row is consumed, DISCARD the staging lines from L2 (dirty scratch:
// no writeback; rewritten by next replay's scan before any read).
#define NORM_TPB 256
#define NORM_ELEMS 32
__global__ __launch_bounds__(NORM_TPB)
void norm_kernel(float* __restrict__ out)
{
    const int row = blockIdx.x;
    const float inv = g_row_inv[row];
    const float neg = -g_mean_val * inv;
    const size_t base = (size_t)row * T_LEN + (size_t)threadIdx.x * NORM_ELEMS;

    const uint4* src = reinterpret_cast<const uint4*>(g_ret_h + base);
    uint4 u[4];
#pragma unroll
    for (int j = 0; j < 4; j++) u[j] = src[j];   // front-batched: MLP=4

    float4* o4 = reinterpret_cast<float4*>(out + base);
#pragma unroll
    for (int j = 0; j < 4; j++) {
        const __half2* h = reinterpret_cast<const __half2*>(&u[j]);
        float4 v;
        float2 a = __half22float2(h[0]);
        float2 b = __half22float2(h[1]);
        v.x = fmaf(a.x, inv, neg); v.y = fmaf(a.y, inv, neg);
        v.z = fmaf(b.x, inv, neg); v.w = fmaf(b.y, inv, neg);
        __stcs(o4 + 2*j, v);
        float2 c = __half22float2(h[2]);
        float2 d = __half22float2(h[3]);
        v.x = fmaf(c.x, inv, neg); v.y = fmaf(c.y, inv, neg);
        v.z = fmaf(d.x, inv, neg); v.w = fmaf(d.y, inv, neg);
        __stcs(o4 + 2*j + 1, v);
    }

    // All of this block's staging reads are complete (values consumed by the
    // stores above); barrier makes that true block-wide before any discard.
    __syncthreads();
    // Each thread covers 64B of staging; even threads discard the shared 128B line.
    if ((threadIdx.x & 1) == 0) {
        const char* p = reinterpret_cast<const char*>(g_ret_h + base);
        asm volatile("discard.global.L2 [%0], 128;" :: "l"(p) : "memory");
    }
}

extern "C" void kernel_launch(void* const* d_in, const int* in_sizes, int n_in,
                              void* d_out, int out_size)
{
    const float* rewards = (const float*)d_in[0];
    const float* dones   = (const float*)d_in[1];
    float* out = (float*)d_out;

    scan_kernel<<<B_ROWS, SCAN_THREADS>>>(rewards, dones);
    norm_kernel<<<B_ROWS, NORM_TPB>>>(out);
}

// round 6
// speedup vs baseline: 1.1861x; 1.1861x over previous
#include <cuda_runtime.h>
#include <cuda_fp16.h>
#include <math.h>

#define B_ROWS 4096
#define T_LEN  8192
#define SCAN_THREADS 512
#define NWARPS (SCAN_THREADS / 32)     // 16
#define CHUNK (T_LEN / SCAN_THREADS)   // 16
#define GAMMA 0.99f
#define GAMMA16 0.8514577710948755f    // 0.99^16
#define EPS_N 1e-9f

// Scratch (device globals; no allocations allowed).
__device__ float    g_row_sum[B_ROWS];
__device__ float    g_row_inv[B_ROWS];
__device__ float    g_mean_val;
__device__ unsigned g_count;           // zero-init; atomicInc wraps -> self-reset per launch
// fp16 staging for unnormalized returns: 64 MB, fits in L2 (126 MB).
__device__ __align__(128) __half g_ret_h[(size_t)B_ROWS * T_LEN];

// ───────────────────────── scan: one block per row ─────────────────────────
// x_t = r_t + a_t * x_{t+1},  a_t = GAMMA*(1-done_t),  done in {0,1} exactly.
__global__ __launch_bounds__(SCAN_THREADS, 3)
void scan_kernel(const float* __restrict__ rewards,
                 const float* __restrict__ dones)
{
    const int row  = blockIdx.x;
    const int tid  = threadIdx.x;
    const int lane = tid & 31;
    const int wid  = tid >> 5;
    const size_t row_off = (size_t)row * T_LEN;
    const int base = tid * CHUNK;

    float r[CHUNK];
    unsigned mask = 0;                 // bit t set -> done_t == 1 -> a_t == 0

    const float4* r4 = reinterpret_cast<const float4*>(rewards + row_off + base);
    const float4* d4 = reinterpret_cast<const float4*>(dones   + row_off + base);
#pragma unroll
    for (int i = 0; i < CHUNK / 4; i++) {
        float4 rv = __ldcs(r4 + i);
        float4 dv = __ldcs(d4 + i);
        r[i*4+0] = rv.x; r[i*4+1] = rv.y; r[i*4+2] = rv.z; r[i*4+3] = rv.w;
        mask |= (dv.x != 0.0f ? 1u : 0u) << (i*4+0);
        mask |= (dv.y != 0.0f ? 1u : 0u) << (i*4+1);
        mask |= (dv.z != 0.0f ? 1u : 0u) << (i*4+2);
        mask |= (dv.w != 0.0f ? 1u : 0u) << (i*4+3);
    }

    // Compose chunk into affine map (A, B): x_left = B + A * x_right.
    float A  = (mask == 0u) ? GAMMA16 : 0.0f;
    float Bc = 0.0f;
#pragma unroll
    for (int t = CHUNK - 1; t >= 0; t--) {
        float f = fmaf(GAMMA, Bc, r[t]);
        Bc = (mask & (1u << t)) ? r[t] : f;
    }

    // Warp-level inclusive SUFFIX scan via shuffles.
#pragma unroll
    for (int d = 1; d < 32; d <<= 1) {
        float A2 = __shfl_down_sync(0xFFFFFFFFu, A, d);
        float B2 = __shfl_down_sync(0xFFFFFFFFu, Bc, d);
        if (lane + d < 32) {
            Bc = fmaf(A, B2, Bc);
            A  = A * A2;
        }
    }

    __shared__ float sWA[NWARPS];
    __shared__ float sWB[NWARPS];
    __shared__ float sCB[NWARPS];
    if (lane == 0) { sWA[wid] = A; sWB[wid] = Bc; }
    __syncthreads();

    if (wid == 0) {
        float wA = (lane < NWARPS) ? sWA[lane] : 1.0f;
        float wB = (lane < NWARPS) ? sWB[lane] : 0.0f;
#pragma unroll
        for (int d = 1; d < NWARPS; d <<= 1) {
            float A2 = __shfl_down_sync(0xFFFFFFFFu, wA, d);
            float B2 = __shfl_down_sync(0xFFFFFFFFu, wB, d);
            if (lane + d < NWARPS) {
                wB = fmaf(wA, B2, wB);
                wA = wA * A2;
            }
        }
        float eB = __shfl_down_sync(0xFFFFFFFFu, wB, 1);
        if (lane == NWARPS - 1) eB = 0.0f;
        if (lane < NWARPS) sCB[lane] = eB;
    }
    __syncthreads();

    float cB   = sCB[wid];
    float totB = fmaf(A, cB, Bc);
    float carry = __shfl_down_sync(0xFFFFFFFFu, totB, 1);
    if (lane == 31) carry = cB;        // tid==511 -> cB==0, correct

    // Replay chunk with true carry; values + row moments (f32 precision).
    float sum = 0.0f, sq = 0.0f;
#pragma unroll
    for (int t = CHUNK - 1; t >= 0; t--) {
        float f = fmaf(GAMMA, carry, r[t]);
        carry = (mask & (1u << t)) ? r[t] : f;
        r[t] = carry;
        sum += carry;
        sq = fmaf(carry, carry, sq);
    }

    // fp16 staging store (default policy -> allocate in L2; consumed by norm).
    __half2 h[CHUNK / 2];
#pragma unroll
    for (int i = 0; i < CHUNK / 2; i++)
        h[i] = __floats2half2_rn(r[2*i], r[2*i+1]);
    uint4* dst = reinterpret_cast<uint4*>(g_ret_h + row_off + base);
    const uint4* src = reinterpret_cast<const uint4*>(h);
    dst[0] = src[0];
    dst[1] = src[1];

    // Block reduction of (sum, sq).
#pragma unroll
    for (int d = 16; d > 0; d >>= 1) {
        sum += __shfl_down_sync(0xFFFFFFFFu, sum, d);
        sq  += __shfl_down_sync(0xFFFFFFFFu, sq,  d);
    }
    __shared__ float sS[NWARPS];
    __shared__ float sQ[NWARPS];
    if (lane == 0) { sS[wid] = sum; sQ[wid] = sq; }
    __syncthreads();
    if (tid < 32) {
        float ts = (lane < NWARPS) ? sS[lane] : 0.0f;
        float tq = (lane < NWARPS) ? sQ[lane] : 0.0f;
#pragma unroll
        for (int d = NWARPS / 2; d > 0; d >>= 1) {
            ts += __shfl_down_sync(0xFFFFFFFFu, ts, d);
            tq += __shfl_down_sync(0xFFFFFFFFu, tq, d);
        }
        if (lane == 0) {
            float mean = ts / (float)T_LEN;
            float var  = (tq - ts * mean) / (float)(T_LEN - 1);   // ddof=1
            g_row_sum[row] = ts;
            g_row_inv[row] = 1.0f / (sqrtf(fmaxf(var, 0.0f)) + EPS_N);
        }
    }

    // Last block to finish reduces the 4096 row sums -> global mean.
    __shared__ unsigned s_last;
    if (tid == 0) {
        __threadfence();
        unsigned prev = atomicInc(&g_count, B_ROWS - 1);
        s_last = (prev == B_ROWS - 1) ? 1u : 0u;
    }
    __syncthreads();
    if (s_last) {
        float s = 0.0f;
#pragma unroll
        for (int i = 0; i < B_ROWS / SCAN_THREADS; i++)
            s += __ldcg(&g_row_sum[tid + i * SCAN_THREADS]);
#pragma unroll
        for (int d = 16; d > 0; d >>= 1)
            s += __shfl_down_sync(0xFFFFFFFFu, s, d);
        if (lane == 0) sS[wid] = s;
        __syncthreads();
        if (tid < 32) {
            float t = (lane < NWARPS) ? sS[lane] : 0.0f;
#pragma unroll
            for (int d = 16; d > 0; d >>= 1)
                t += __shfl_down_sync(0xFFFFFFFFu, t, d);
            if (tid == 0)
                g_mean_val = t / ((float)B_ROWS * (float)T_LEN);
        }
    }
}

// ── normalize: read fp16 staging (L2-resident), write f32 out (streaming) ──
// 512 threads/block, 32 elements/thread (4 independent uint4 loads, MLP=4),
// grid 2048. No discard (R5 showed it throttles LTS). Each thread's 32
// elements stay inside one row (32 | 8192).
#define NORM_TPB 512
#define NORM_ELEMS 32
__global__ __launch_bounds__(NORM_TPB)
void norm_kernel(float* __restrict__ out)
{
    const int i = blockIdx.x * blockDim.x + threadIdx.x;
    const size_t base = (size_t)i * NORM_ELEMS;
    const int row = (int)(base >> 13);           // / T_LEN
    const float inv = g_row_inv[row];
    const float neg = -g_mean_val * inv;

    const uint4* src = reinterpret_cast<const uint4*>(g_ret_h + base);
    uint4 u[4];
#pragma unroll
    for (int j = 0; j < 4; j++) u[j] = src[j];   // front-batched: MLP=4

    float4* o4 = reinterpret_cast<float4*>(out + base);
#pragma unroll
    for (int j = 0; j < 4; j++) {
        const __half2* h = reinterpret_cast<const __half2*>(&u[j]);
        float4 v;
        float2 a = __half22float2(h[0]);
        float2 b = __half22float2(h[1]);
        v.x = fmaf(a.x, inv, neg); v.y = fmaf(a.y, inv, neg);
        v.z = fmaf(b.x, inv, neg); v.w = fmaf(b.y, inv, neg);
        __stcs(o4 + 2*j, v);
        float2 c = __half22float2(h[2]);
        float2 d = __half22float2(h[3]);
        v.x = fmaf(c.x, inv, neg); v.y = fmaf(c.y, inv, neg);
        v.z = fmaf(d.x, inv, neg); v.w = fmaf(d.y, inv, neg);
        __stcs(o4 + 2*j + 1, v);
    }
}

extern "C" void kernel_launch(void* const* d_in, const int* in_sizes, int n_in,
                              void* d_out, int out_size)
{
    const float* rewards = (const float*)d_in[0];
    const float* dones   = (const float*)d_in[1];
    float* out = (float*)d_out;

    scan_kernel<<<B_ROWS, SCAN_THREADS>>>(rewards, dones);
    const int nthreads = B_ROWS * (T_LEN / NORM_ELEMS);   // 1M
    norm_kernel<<<nthreads / NORM_TPB, NORM_TPB>>>(out);
}

// round 7
// speedup vs baseline: 1.2535x; 1.0569x over previous
#include <cuda_runtime.h>
#include <cuda_fp16.h>
#include <math.h>

#define B_ROWS 4096
#define T_LEN  8192
#define SCAN_THREADS 512
#define NWARPS (SCAN_THREADS / 32)     // 16
#define CHUNK (T_LEN / SCAN_THREADS)   // 16
#define GAMMA 0.99f
#define GAMMA16 0.8514577710948755f    // 0.99^16
#define EPS_N 1e-9f

#define SCAN_GRID (148 * 3)            // persistent: 3 CTAs/SM
#define NORM_GRID (148 * 4)            // persistent: 4 CTAs/SM

// Scratch (device globals; no allocations allowed).
__device__ float    g_row_sum[B_ROWS];
__device__ float    g_row_inv[B_ROWS];
__device__ float    g_mean_val;
__device__ unsigned g_count;           // zero-init; atomicInc wraps -> self-reset per launch
// fp16 staging for unnormalized returns: 64 MB, stays L2-resident across replays
// (everything else streams with ldcs/stcs, and each replay re-dirties the same lines).
__device__ __align__(128) __half g_ret_h[(size_t)B_ROWS * T_LEN];

// ─────────────── scan: persistent, one block-iteration per row ───────────────
// x_t = r_t + a_t * x_{t+1},  a_t = GAMMA*(1-done_t),  done in {0,1} exactly.
__global__ __launch_bounds__(SCAN_THREADS, 3)
void scan_kernel(const float* __restrict__ rewards,
                 const float* __restrict__ dones)
{
    const int tid  = threadIdx.x;
    const int lane = tid & 31;
    const int wid  = tid >> 5;
    const int base = tid * CHUNK;

    __shared__ float sWA[NWARPS];
    __shared__ float sWB[NWARPS];
    __shared__ float sCB[NWARPS];
    __shared__ float sS[NWARPS];
    __shared__ float sQ[NWARPS];
    __shared__ unsigned s_last;

    for (int row = blockIdx.x; row < B_ROWS; row += SCAN_GRID) {
        const size_t row_off = (size_t)row * T_LEN;

        float r[CHUNK];
        unsigned mask = 0;             // bit t set -> done_t == 1 -> a_t == 0

        const float4* r4 = reinterpret_cast<const float4*>(rewards + row_off + base);
        const float4* d4 = reinterpret_cast<const float4*>(dones   + row_off + base);
        // Front-batched streaming loads (read-once data).
        float4 rv[CHUNK / 4], dv[CHUNK / 4];
#pragma unroll
        for (int i = 0; i < CHUNK / 4; i++) rv[i] = __ldcs(r4 + i);
#pragma unroll
        for (int i = 0; i < CHUNK / 4; i++) dv[i] = __ldcs(d4 + i);
#pragma unroll
        for (int i = 0; i < CHUNK / 4; i++) {
            r[i*4+0] = rv[i].x; r[i*4+1] = rv[i].y; r[i*4+2] = rv[i].z; r[i*4+3] = rv[i].w;
            mask |= (dv[i].x != 0.0f ? 1u : 0u) << (i*4+0);
            mask |= (dv[i].y != 0.0f ? 1u : 0u) << (i*4+1);
            mask |= (dv[i].z != 0.0f ? 1u : 0u) << (i*4+2);
            mask |= (dv[i].w != 0.0f ? 1u : 0u) << (i*4+3);
        }

        // Compose chunk into affine map (A, B): x_left = B + A * x_right.
        float A  = (mask == 0u) ? GAMMA16 : 0.0f;
        float Bc = 0.0f;
#pragma unroll
        for (int t = CHUNK - 1; t >= 0; t--) {
            float f = fmaf(GAMMA, Bc, r[t]);
            Bc = (mask & (1u << t)) ? r[t] : f;
        }

        // Warp-level inclusive SUFFIX scan via shuffles.
#pragma unroll
        for (int d = 1; d < 32; d <<= 1) {
            float A2 = __shfl_down_sync(0xFFFFFFFFu, A, d);
            float B2 = __shfl_down_sync(0xFFFFFFFFu, Bc, d);
            if (lane + d < 32) {
                Bc = fmaf(A, B2, Bc);
                A  = A * A2;
            }
        }

        if (lane == 0) { sWA[wid] = A; sWB[wid] = Bc; }
        __syncthreads();

        if (wid == 0) {
            float wA = (lane < NWARPS) ? sWA[lane] : 1.0f;
            float wB = (lane < NWARPS) ? sWB[lane] : 0.0f;
#pragma unroll
            for (int d = 1; d < NWARPS; d <<= 1) {
                float A2 = __shfl_down_sync(0xFFFFFFFFu, wA, d);
                float B2 = __shfl_down_sync(0xFFFFFFFFu, wB, d);
                if (lane + d < NWARPS) {
                    wB = fmaf(wA, B2, wB);
                    wA = wA * A2;
                }
            }
            float eB = __shfl_down_sync(0xFFFFFFFFu, wB, 1);
            if (lane == NWARPS - 1) eB = 0.0f;
            if (lane < NWARPS) sCB[lane] = eB;
        }
        __syncthreads();

        float cB   = sCB[wid];
        float totB = fmaf(A, cB, Bc);
        float carry = __shfl_down_sync(0xFFFFFFFFu, totB, 1);
        if (lane == 31) carry = cB;    // tid==511 -> cB==0, correct

        // Replay chunk with true carry; values + row moments (f32 precision).
        float sum = 0.0f, sq = 0.0f;
#pragma unroll
        for (int t = CHUNK - 1; t >= 0; t--) {
            float f = fmaf(GAMMA, carry, r[t]);
            carry = (mask & (1u << t)) ? r[t] : f;
            r[t] = carry;
            sum += carry;
            sq = fmaf(carry, carry, sq);
        }

        // fp16 staging store (default policy -> allocate in L2; consumed by norm).
        __half2 h[CHUNK / 2];
#pragma unroll
        for (int i = 0; i < CHUNK / 2; i++)
            h[i] = __floats2half2_rn(r[2*i], r[2*i+1]);
        uint4* dst = reinterpret_cast<uint4*>(g_ret_h + row_off + base);
        const uint4* src = reinterpret_cast<const uint4*>(h);
        dst[0] = src[0];
        dst[1] = src[1];

        // Block reduction of (sum, sq).
#pragma unroll
        for (int d = 16; d > 0; d >>= 1) {
            sum += __shfl_down_sync(0xFFFFFFFFu, sum, d);
            sq  += __shfl_down_sync(0xFFFFFFFFu, sq,  d);
        }
        if (lane == 0) { sS[wid] = sum; sQ[wid] = sq; }
        __syncthreads();
        if (tid < 32) {
            float ts = (lane < NWARPS) ? sS[lane] : 0.0f;
            float tq = (lane < NWARPS) ? sQ[lane] : 0.0f;
#pragma unroll
            for (int d = NWARPS / 2; d > 0; d >>= 1) {
                ts += __shfl_down_sync(0xFFFFFFFFu, ts, d);
                tq += __shfl_down_sync(0xFFFFFFFFu, tq, d);
            }
            if (lane == 0) {
                float mean = ts / (float)T_LEN;
                float var  = (tq - ts * mean) / (float)(T_LEN - 1);   // ddof=1
                g_row_sum[row] = ts;
                g_row_inv[row] = 1.0f / (sqrtf(fmaxf(var, 0.0f)) + EPS_N);
            }
        }

        // Completion ticket: exactly B_ROWS increments per launch; the row that
        // lands the final ticket reduces the 4096 row sums -> global mean.
        if (tid == 0) {
            __threadfence();
            unsigned prev = atomicInc(&g_count, B_ROWS - 1);   // wraps to 0: self-reset
            s_last = (prev == B_ROWS - 1) ? 1u : 0u;
        }
        __syncthreads();
        if (s_last) {
            float s = 0.0f;
#pragma unroll
            for (int i = 0; i < B_ROWS / SCAN_THREADS; i++)
                s += __ldcg(&g_row_sum[tid + i * SCAN_THREADS]);
#pragma unroll
            for (int d = 16; d > 0; d >>= 1)
                s += __shfl_down_sync(0xFFFFFFFFu, s, d);
            if (lane == 0) sS[wid] = s;
            __syncthreads();
            if (tid < 32) {
                float t = (lane < NWARPS) ? sS[lane] : 0.0f;
#pragma unroll
                for (int d = 16; d > 0; d >>= 1)
                    t += __shfl_down_sync(0xFFFFFFFFu, t, d);
                if (tid == 0)
                    g_mean_val = t / ((float)B_ROWS * (float)T_LEN);
            }
            __syncthreads();   // keep sS reuse safe on next loop iteration
        }
    }
}

// ── normalize: persistent; read fp16 staging (L2-resident), write f32 (streaming) ──
// R4-proven inner config: 512 threads, 16 elements/thread (2 uint4 loads, MLP=2).
#define NORM_TPB 512
#define NORM_ELEMS 16
#define NORM_TILES (B_ROWS * T_LEN / (NORM_TPB * NORM_ELEMS))   // 4096
__global__ __launch_bounds__(NORM_TPB, 4)
void norm_kernel(float* __restrict__ out)
{
    const float gmean = g_mean_val;
    for (int tile = blockIdx.x; tile < NORM_TILES; tile += NORM_GRID) {
        const size_t base = ((size_t)tile * NORM_TPB + threadIdx.x) * NORM_ELEMS;
        const int row = (int)(base >> 13);       // / T_LEN
        const float inv = g_row_inv[row];
        const float neg = -gmean * inv;

        const uint4* src = reinterpret_cast<const uint4*>(g_ret_h + base);
        uint4 u0 = src[0];
        uint4 u1 = src[1];

        const __half2* h0 = reinterpret_cast<const __half2*>(&u0);
        const __half2* h1 = reinterpret_cast<const __half2*>(&u1);

        float4* o4 = reinterpret_cast<float4*>(out + base);
        float4 v;
#pragma unroll
        for (int j = 0; j < 2; j++) {
            float2 a = __half22float2(h0[2*j+0]);
            float2 b = __half22float2(h0[2*j+1]);
            v.x = fmaf(a.x, inv, neg); v.y = fmaf(a.y, inv, neg);
            v.z = fmaf(b.x, inv, neg); v.w = fmaf(b.y, inv, neg);
            __stcs(o4 + j, v);
        }
#pragma unroll
        for (int j = 0; j < 2; j++) {
            float2 a = __half22float2(h1[2*j+0]);
            float2 b = __half22float2(h1[2*j+1]);
            v.x = fmaf(a.x, inv, neg); v.y = fmaf(a.y, inv, neg);
            v.z = fmaf(b.x, inv, neg); v.w = fmaf(b.y, inv, neg);
            __stcs(o4 + 2 + j, v);
        }
    }
}

extern "C" void kernel_launch(void* const* d_in, const int* in_sizes, int n_in,
                              void* d_out, int out_size)
{
    const float* rewards = (const float*)d_in[0];
    const float* dones   = (const float*)d_in[1];
    float* out = (float*)d_out;

    scan_kernel<<<SCAN_GRID, SCAN_THREADS>>>(rewards, dones);
    norm_kernel<<<NORM_GRID, NORM_TPB>>>(out);
}

// round 8
// speedup vs baseline: 1.3519x; 1.0785x over previous
#include <cuda_runtime.h>
#include <cuda_fp16.h>
#include <math.h>

#define B_ROWS 4096
#define T_LEN  8192
#define SCAN_THREADS 512
#define NWARPS (SCAN_THREADS / 32)     // 16
#define CHUNK (T_LEN / SCAN_THREADS)   // 16
#define GAMMA 0.99f
#define GAMMA16 0.8514577710948755f    // 0.99^16
#define EPS_N 1e-9f

// Scratch (device globals; no allocations allowed).
__device__ float    g_row_sum[B_ROWS];
__device__ float    g_row_inv[B_ROWS];
__device__ float    g_mean_val;
__device__ unsigned g_count;           // zero-init; atomicInc wraps -> self-reset per launch
// fp16 staging for unnormalized returns: 64 MB, fits in L2 (126 MB).
__device__ __align__(128) __half g_ret_h[(size_t)B_ROWS * T_LEN];

// ───────────────────────── scan: one block per row ─────────────────────────
// x_t = r_t + a_t * x_{t+1},  a_t = GAMMA*(1-done_t),  done in {0,1} exactly.
__global__ __launch_bounds__(SCAN_THREADS, 3)
void scan_kernel(const float* __restrict__ rewards,
                 const float* __restrict__ dones)
{
    const int row  = blockIdx.x;
    const int tid  = threadIdx.x;
    const int lane = tid & 31;
    const int wid  = tid >> 5;
    const size_t row_off = (size_t)row * T_LEN;
    const int base = tid * CHUNK;

    float r[CHUNK];
    unsigned mask = 0;                 // bit t set -> done_t == 1 -> a_t == 0

    const float4* r4 = reinterpret_cast<const float4*>(rewards + row_off + base);
    const float4* d4 = reinterpret_cast<const float4*>(dones   + row_off + base);
#pragma unroll
    for (int i = 0; i < CHUNK / 4; i++) {
        float4 rv = __ldcs(r4 + i);
        float4 dv = __ldcs(d4 + i);
        r[i*4+0] = rv.x; r[i*4+1] = rv.y; r[i*4+2] = rv.z; r[i*4+3] = rv.w;
        mask |= (dv.x != 0.0f ? 1u : 0u) << (i*4+0);
        mask |= (dv.y != 0.0f ? 1u : 0u) << (i*4+1);
        mask |= (dv.z != 0.0f ? 1u : 0u) << (i*4+2);
        mask |= (dv.w != 0.0f ? 1u : 0u) << (i*4+3);
    }

    // Compose chunk into affine map (A, B): x_left = B + A * x_right.
    float A  = (mask == 0u) ? GAMMA16 : 0.0f;
    float Bc = 0.0f;
#pragma unroll
    for (int t = CHUNK - 1; t >= 0; t--) {
        float f = fmaf(GAMMA, Bc, r[t]);
        Bc = (mask & (1u << t)) ? r[t] : f;
    }

    // Warp-level inclusive SUFFIX scan via shuffles.
#pragma unroll
    for (int d = 1; d < 32; d <<= 1) {
        float A2 = __shfl_down_sync(0xFFFFFFFFu, A, d);
        float B2 = __shfl_down_sync(0xFFFFFFFFu, Bc, d);
        if (lane + d < 32) {
            Bc = fmaf(A, B2, Bc);
            A  = A * A2;
        }
    }

    __shared__ float sWA[NWARPS];
    __shared__ float sWB[NWARPS];
    __shared__ float sCB[NWARPS];
    if (lane == 0) { sWA[wid] = A; sWB[wid] = Bc; }
    __syncthreads();

    if (wid == 0) {
        float wA = (lane < NWARPS) ? sWA[lane] : 1.0f;
        float wB = (lane < NWARPS) ? sWB[lane] : 0.0f;
#pragma unroll
        for (int d = 1; d < NWARPS; d <<= 1) {
            float A2 = __shfl_down_sync(0xFFFFFFFFu, wA, d);
            float B2 = __shfl_down_sync(0xFFFFFFFFu, wB, d);
            if (lane + d < NWARPS) {
                wB = fmaf(wA, B2, wB);
                wA = wA * A2;
            }
        }
        float eB = __shfl_down_sync(0xFFFFFFFFu, wB, 1);
        if (lane == NWARPS - 1) eB = 0.0f;
        if (lane < NWARPS) sCB[lane] = eB;
    }
    __syncthreads();

    float cB   = sCB[wid];
    float totB = fmaf(A, cB, Bc);
    float carry = __shfl_down_sync(0xFFFFFFFFu, totB, 1);
    if (lane == 31) carry = cB;        // tid==511 -> cB==0, correct

    // Replay chunk with true carry; values + row moments (f32 precision).
    float sum = 0.0f, sq = 0.0f;
#pragma unroll
    for (int t = CHUNK - 1; t >= 0; t--) {
        float f = fmaf(GAMMA, carry, r[t]);
        carry = (mask & (1u << t)) ? r[t] : f;
        r[t] = carry;
        sum += carry;
        sq = fmaf(carry, carry, sq);
    }

    // fp16 staging store (default policy -> allocate in L2; consumed by norm).
    __half2 h[CHUNK / 2];
#pragma unroll
    for (int i = 0; i < CHUNK / 2; i++)
        h[i] = __floats2half2_rn(r[2*i], r[2*i+1]);
    uint4* dst = reinterpret_cast<uint4*>(g_ret_h + row_off + base);
    const uint4* src = reinterpret_cast<const uint4*>(h);
    dst[0] = src[0];
    dst[1] = src[1];

    // Block reduction of (sum, sq).
#pragma unroll
    for (int d = 16; d > 0; d >>= 1) {
        sum += __shfl_down_sync(0xFFFFFFFFu, sum, d);
        sq  += __shfl_down_sync(0xFFFFFFFFu, sq,  d);
    }
    __shared__ float sS[NWARPS];
    __shared__ float sQ[NWARPS];
    if (lane == 0) { sS[wid] = sum; sQ[wid] = sq; }
    __syncthreads();
    if (tid < 32) {
        float ts = (lane < NWARPS) ? sS[lane] : 0.0f;
        float tq = (lane < NWARPS) ? sQ[lane] : 0.0f;
#pragma unroll
        for (int d = NWARPS / 2; d > 0; d >>= 1) {
            ts += __shfl_down_sync(0xFFFFFFFFu, ts, d);
            tq += __shfl_down_sync(0xFFFFFFFFu, tq, d);
        }
        if (lane == 0) {
            float mean = ts / (float)T_LEN;
            float var  = (tq - ts * mean) / (float)(T_LEN - 1);   // ddof=1
            g_row_sum[row] = ts;
            g_row_inv[row] = 1.0f / (sqrtf(fmaxf(var, 0.0f)) + EPS_N);
        }
    }

    // Last block to finish reduces the 4096 row sums -> global mean.
    __shared__ unsigned s_last;
    if (tid == 0) {
        __threadfence();
        unsigned prev = atomicInc(&g_count, B_ROWS - 1);
        s_last = (prev == B_ROWS - 1) ? 1u : 0u;
    }
    __syncthreads();
    if (s_last) {
        float s = 0.0f;
#pragma unroll
        for (int i = 0; i < B_ROWS / SCAN_THREADS; i++)
            s += __ldcg(&g_row_sum[tid + i * SCAN_THREADS]);
#pragma unroll
        for (int d = 16; d > 0; d >>= 1)
            s += __shfl_down_sync(0xFFFFFFFFu, s, d);
        if (lane == 0) sS[wid] = s;
        __syncthreads();
        if (tid < 32) {
            float t = (lane < NWARPS) ? sS[lane] : 0.0f;
#pragma unroll
            for (int d = 16; d > 0; d >>= 1)
                t += __shfl_down_sync(0xFFFFFFFFu, t, d);
            if (tid == 0)
                g_mean_val = t / ((float)B_ROWS * (float)T_LEN);
        }
    }
}

// ── normalize: read fp16 staging (L2-resident, LAST-USE), write f32 (streaming) ──
// R4-proven config: 512 threads, 16 elements/thread (2 uint4 loads, MLP=2).
// __ldlu marks staging lines evict-first after their single read, easing the
// cross-replay dirty-writeback pressure on the following scan.
#define NORM_ELEMS 16
__global__ __launch_bounds__(512)
void norm_kernel(float* __restrict__ out)
{
    const float gmean = g_mean_val;
    const int i = blockIdx.x * blockDim.x + threadIdx.x;
    const size_t base = (size_t)i * NORM_ELEMS;
    const int row = (int)(base >> 13);           // / T_LEN
    const float inv = g_row_inv[row];
    const float neg = -gmean * inv;

    const uint4* src = reinterpret_cast<const uint4*>(g_ret_h + base);
    uint4 u0 = __ldlu(src + 0);
    uint4 u1 = __ldlu(src + 1);

    const __half2* h0 = reinterpret_cast<const __half2*>(&u0);
    const __half2* h1 = reinterpret_cast<const __half2*>(&u1);

    float4* o4 = reinterpret_cast<float4*>(out + base);
    float4 v;
#pragma unroll
    for (int j = 0; j < 2; j++) {
        float2 a = __half22float2(h0[2*j+0]);
        float2 b = __half22float2(h0[2*j+1]);
        v.x = fmaf(a.x, inv, neg); v.y = fmaf(a.y, inv, neg);
        v.z = fmaf(b.x, inv, neg); v.w = fmaf(b.y, inv, neg);
        __stcs(o4 + j, v);
    }
#pragma unroll
    for (int j = 0; j < 2; j++) {
        float2 a = __half22float2(h1[2*j+0]);
        float2 b = __half22float2(h1[2*j+1]);
        v.x = fmaf(a.x, inv, neg); v.y = fmaf(a.y, inv, neg);
        v.z = fmaf(b.x, inv, neg); v.w = fmaf(b.y, inv, neg);
        __stcs(o4 + 2 + j, v);
    }
}

extern "C" void kernel_launch(void* const* d_in, const int* in_sizes, int n_in,
                              void* d_out, int out_size)
{
    const float* rewards = (const float*)d_in[0];
    const float* dones   = (const float*)d_in[1];
    float* out = (float*)d_out;

    scan_kernel<<<B_ROWS, SCAN_THREADS>>>(rewards, dones);
    const int nthreads = B_ROWS * (T_LEN / NORM_ELEMS);   // 2M
    norm_kernel<<<nthreads / 512, 512>>>(out);
}